// round 10
// baseline (speedup 1.0000x reference)
#include <cuda_runtime.h>
#include <cuda_bf16.h>
#include <cstdint>

// Inputs (metadata order):
//   d_in[0] features  float32 [E*5]
//   d_in[1] values    float32 [E]
//   d_in[2] a0_weight float32 [5]
//   d_in[3] rows      int32   [E]
//   d_in[4] num_nodes int32   [1]
// Output: float32 [num_nodes]

// Single zeroing kernel (grid-stride, vectorized + tail handled inline).
__global__ void zero_all_kernel(float* __restrict__ out, int n) {
    int n4 = n >> 2;
    float4* out4 = (float4*)out;
    int i = blockIdx.x * blockDim.x + threadIdx.x;
    int stride = gridDim.x * blockDim.x;
    for (int j = i; j < n4; j += stride)
        out4[j] = make_float4(0.f, 0.f, 0.f, 0.f);
    // tail
    int t = n4 * 4 + i;
    if (t < n) out[t] = 0.f;
}

// One-shot: each thread owns 8 consecutive edges (two "quads").
// 14 front-batched wide streaming loads, then 8 REDGs.
__global__ __launch_bounds__(128) void scatter_dot_vec8_kernel(
    const float4* __restrict__ feat4,  // [E*5/4]
    const float4* __restrict__ vals4,  // [E/4]
    const float*  __restrict__ w,      // [5]
    const int4*   __restrict__ rows4,  // [E/4]
    float* __restrict__ out,
    int nOcts)                         // E/8
{
    const float w0 = __ldg(w + 0);
    const float w1 = __ldg(w + 1);
    const float w2 = __ldg(w + 2);
    const float w3 = __ldg(w + 3);
    const float w4 = __ldg(w + 4);

    int t = blockIdx.x * blockDim.x + threadIdx.x;
    if (t >= nOcts) return;

    const size_t fb = (size_t)t * 10;   // 10 float4 = 40 floats = 8 rows x 5
    const float4 f0 = __ldcs(feat4 + fb + 0);
    const float4 f1 = __ldcs(feat4 + fb + 1);
    const float4 f2 = __ldcs(feat4 + fb + 2);
    const float4 f3 = __ldcs(feat4 + fb + 3);
    const float4 f4 = __ldcs(feat4 + fb + 4);
    const float4 f5 = __ldcs(feat4 + fb + 5);
    const float4 f6 = __ldcs(feat4 + fb + 6);
    const float4 f7 = __ldcs(feat4 + fb + 7);
    const float4 f8 = __ldcs(feat4 + fb + 8);
    const float4 f9 = __ldcs(feat4 + fb + 9);
    const float4 va = __ldcs(vals4 + (size_t)t * 2 + 0);
    const float4 vb = __ldcs(vals4 + (size_t)t * 2 + 1);
    const int4   ra = __ldcs(rows4 + (size_t)t * 2 + 0);
    const int4   rb = __ldcs(rows4 + (size_t)t * 2 + 1);

    // edges 0..3  (floats 0..19  = f0..f4)
    float d0 = w0*f0.x + w1*f0.y + w2*f0.z + w3*f0.w + w4*f1.x;
    float d1 = w0*f1.y + w1*f1.z + w2*f1.w + w3*f2.x + w4*f2.y;
    float d2 = w0*f2.z + w1*f2.w + w2*f3.x + w3*f3.y + w4*f3.z;
    float d3 = w0*f3.w + w1*f4.x + w2*f4.y + w3*f4.z + w4*f4.w;
    // edges 4..7  (floats 20..39 = f5..f9)
    float d4 = w0*f5.x + w1*f5.y + w2*f5.z + w3*f5.w + w4*f6.x;
    float d5 = w0*f6.y + w1*f6.z + w2*f6.w + w3*f7.x + w4*f7.y;
    float d6 = w0*f7.z + w1*f7.w + w2*f8.x + w3*f8.y + w4*f8.z;
    float d7 = w0*f8.w + w1*f9.x + w2*f9.y + w3*f9.z + w4*f9.w;

    atomicAdd(out + ra.x, va.x * d0);
    atomicAdd(out + ra.y, va.y * d1);
    atomicAdd(out + ra.z, va.z * d2);
    atomicAdd(out + ra.w, va.w * d3);
    atomicAdd(out + rb.x, vb.x * d4);
    atomicAdd(out + rb.y, vb.y * d5);
    atomicAdd(out + rb.z, vb.z * d6);
    atomicAdd(out + rb.w, vb.w * d7);
}

// Scalar tail for E % 8 != 0 (not hit for E = 2^24, kept for generality).
__global__ void scatter_dot_tail_kernel(
    const float* __restrict__ feat,
    const float* __restrict__ vals,
    const float* __restrict__ w,
    const int*   __restrict__ rows,
    float* __restrict__ out,
    int start, int E)
{
    int e = start + blockIdx.x * blockDim.x + threadIdx.x;
    if (e >= E) return;
    const float* f = feat + (size_t)e * 5;
    float d = vals[e] * (w[0]*f[0] + w[1]*f[1] + w[2]*f[2] + w[3]*f[3] + w[4]*f[4]);
    atomicAdd(out + rows[e], d);
}

extern "C" void kernel_launch(void* const* d_in, const int* in_sizes, int n_in,
                              void* d_out, int out_size)
{
    const float* feat = (const float*)d_in[0];
    const float* vals = (const float*)d_in[1];
    const float* w    = (const float*)d_in[2];
    const int*   rows = (const int*)d_in[3];
    float* out = (float*)d_out;

    const int E = in_sizes[1];          // values has E elements
    const int N = out_size;             // num_nodes

    // Zero the (poisoned) output: one launch.
    {
        int zb = 256;
        int zg = ((N >> 2) + zb - 1) / zb;
        if (zg < 1) zg = 1;
        zero_all_kernel<<<zg, zb>>>(out, N);
    }

    const int nOcts = E / 8;
    if (nOcts > 0) {
        const int threads = 128;
        const int blocks = (nOcts + threads - 1) / threads;
        scatter_dot_vec8_kernel<<<blocks, threads>>>(
            (const float4*)feat, (const float4*)vals, w, (const int4*)rows,
            out, nOcts);
    }
    const int tailStart = nOcts * 8;
    if (E - tailStart > 0) {
        int n = E - tailStart;
        scatter_dot_tail_kernel<<<(n + 255) / 256, 256>>>(
            feat, vals, w, rows, out, tailStart, E);
    }
}

// round 11
// speedup vs baseline: 1.3367x; 1.3367x over previous
#include <cuda_runtime.h>
#include <cuda_bf16.h>
#include <cstdint>

// Inputs (metadata order):
//   d_in[0] features  float32 [E*5]
//   d_in[1] values    float32 [E]
//   d_in[2] a0_weight float32 [5]
//   d_in[3] rows      int32   [E]
//   d_in[4] num_nodes int32   [1]
// Output: float32 [num_nodes]

__global__ void zero_all_kernel(float* __restrict__ out, int n) {
    int n4 = n >> 2;
    float4* out4 = (float4*)out;
    int i = blockIdx.x * blockDim.x + threadIdx.x;
    if (i < n4)
        out4[i] = make_float4(0.f, 0.f, 0.f, 0.f);
    int t = n4 * 4 + i;
    if (t < n) out[t] = 0.f;
}

// Each thread owns TWO quads: q and q+half (grid-strided pair).
// Keeps the vec4 memory layout (80B lane stride per LDG -> low L1 replay)
// while front-batching 14 wide loads and issuing 8 REDGs per scoreboard
// drain (longer atomic bursts -> better LTS duty cycle).
__global__ __launch_bounds__(128) void scatter_dot_vec4x2_kernel(
    const float4* __restrict__ feat4,  // [E*5/4]
    const float4* __restrict__ vals4,  // [E/4]
    const float*  __restrict__ w,      // [5]
    const int4*   __restrict__ rows4,  // [E/4]
    float* __restrict__ out,
    int half,                          // nQuads/2
    int nQuads)
{
    const float w0 = __ldg(w + 0);
    const float w1 = __ldg(w + 1);
    const float w2 = __ldg(w + 2);
    const float w3 = __ldg(w + 3);
    const float w4 = __ldg(w + 4);

    int qa = blockIdx.x * blockDim.x + threadIdx.x;
    if (qa >= half) return;
    int qb = qa + half;       // second quad, far-strided (same lane stride 80B)

    // Front-batched wide streaming loads for BOTH quads (max MLP).
    const size_t fa = (size_t)qa * 5;
    const float4 a0 = __ldcs(feat4 + fa + 0);
    const float4 a1 = __ldcs(feat4 + fa + 1);
    const float4 a2 = __ldcs(feat4 + fa + 2);
    const float4 a3 = __ldcs(feat4 + fa + 3);
    const float4 a4 = __ldcs(feat4 + fa + 4);
    const size_t fb = (size_t)qb * 5;
    const float4 b0 = __ldcs(feat4 + fb + 0);
    const float4 b1 = __ldcs(feat4 + fb + 1);
    const float4 b2 = __ldcs(feat4 + fb + 2);
    const float4 b3 = __ldcs(feat4 + fb + 3);
    const float4 b4 = __ldcs(feat4 + fb + 4);
    const float4 va = __ldcs(vals4 + qa);
    const float4 vb = __ldcs(vals4 + qb);
    const int4   ra = __ldcs(rows4 + qa);
    const int4   rb = __ldcs(rows4 + qb);

    float d0 = w0*a0.x + w1*a0.y + w2*a0.z + w3*a0.w + w4*a1.x;
    float d1 = w0*a1.y + w1*a1.z + w2*a1.w + w3*a2.x + w4*a2.y;
    float d2 = w0*a2.z + w1*a2.w + w2*a3.x + w3*a3.y + w4*a3.z;
    float d3 = w0*a3.w + w1*a4.x + w2*a4.y + w3*a4.z + w4*a4.w;

    float e0 = w0*b0.x + w1*b0.y + w2*b0.z + w3*b0.w + w4*b1.x;
    float e1 = w0*b1.y + w1*b1.z + w2*b1.w + w3*b2.x + w4*b2.y;
    float e2 = w0*b2.z + w1*b2.w + w2*b3.x + w3*b3.y + w4*b3.z;
    float e3 = w0*b3.w + w1*b4.x + w2*b4.y + w3*b4.z + w4*b4.w;

    atomicAdd(out + ra.x, va.x * d0);
    atomicAdd(out + ra.y, va.y * d1);
    atomicAdd(out + ra.z, va.z * d2);
    atomicAdd(out + ra.w, va.w * d3);
    atomicAdd(out + rb.x, vb.x * e0);
    atomicAdd(out + rb.y, vb.y * e1);
    atomicAdd(out + rb.z, vb.z * e2);
    atomicAdd(out + rb.w, vb.w * e3);
}

// Single-quad kernel for an odd leftover quad range [start, nQuads).
__global__ __launch_bounds__(128) void scatter_dot_vec4_kernel(
    const float4* __restrict__ feat4,
    const float4* __restrict__ vals4,
    const float*  __restrict__ w,
    const int4*   __restrict__ rows4,
    float* __restrict__ out,
    int start, int nQuads)
{
    const float w0 = __ldg(w + 0);
    const float w1 = __ldg(w + 1);
    const float w2 = __ldg(w + 2);
    const float w3 = __ldg(w + 3);
    const float w4 = __ldg(w + 4);

    int q = start + blockIdx.x * blockDim.x + threadIdx.x;
    if (q >= nQuads) return;

    const float4 f0 = __ldcs(feat4 + (size_t)q * 5 + 0);
    const float4 f1 = __ldcs(feat4 + (size_t)q * 5 + 1);
    const float4 f2 = __ldcs(feat4 + (size_t)q * 5 + 2);
    const float4 f3 = __ldcs(feat4 + (size_t)q * 5 + 3);
    const float4 f4 = __ldcs(feat4 + (size_t)q * 5 + 4);
    const float4 v  = __ldcs(vals4 + q);
    const int4   r  = __ldcs(rows4 + q);

    float d0 = w0*f0.x + w1*f0.y + w2*f0.z + w3*f0.w + w4*f1.x;
    float d1 = w0*f1.y + w1*f1.z + w2*f1.w + w3*f2.x + w4*f2.y;
    float d2 = w0*f2.z + w1*f2.w + w2*f3.x + w3*f3.y + w4*f3.z;
    float d3 = w0*f3.w + w1*f4.x + w2*f4.y + w3*f4.z + w4*f4.w;

    atomicAdd(out + r.x, v.x * d0);
    atomicAdd(out + r.y, v.y * d1);
    atomicAdd(out + r.z, v.z * d2);
    atomicAdd(out + r.w, v.w * d3);
}

// Scalar tail for E % 4 != 0.
__global__ void scatter_dot_tail_kernel(
    const float* __restrict__ feat,
    const float* __restrict__ vals,
    const float* __restrict__ w,
    const int*   __restrict__ rows,
    float* __restrict__ out,
    int start, int E)
{
    int e = start + blockIdx.x * blockDim.x + threadIdx.x;
    if (e >= E) return;
    const float* f = feat + (size_t)e * 5;
    float d = vals[e] * (w[0]*f[0] + w[1]*f[1] + w[2]*f[2] + w[3]*f[3] + w[4]*f[4]);
    atomicAdd(out + rows[e], d);
}

extern "C" void kernel_launch(void* const* d_in, const int* in_sizes, int n_in,
                              void* d_out, int out_size)
{
    const float* feat = (const float*)d_in[0];
    const float* vals = (const float*)d_in[1];
    const float* w    = (const float*)d_in[2];
    const int*   rows = (const int*)d_in[3];
    float* out = (float*)d_out;

    const int E = in_sizes[1];          // values has E elements
    const int N = out_size;             // num_nodes

    // Zero the (poisoned) output: one launch.
    {
        int zb = 256;
        int zg = (((N >> 2) ? (N >> 2) : 1) + zb - 1) / zb;
        zero_all_kernel<<<zg, zb>>>(out, N);
    }

    const int nQuads = E / 4;
    const int half = nQuads / 2;
    if (half > 0) {
        const int threads = 128;
        const int blocks = (half + threads - 1) / threads;
        scatter_dot_vec4x2_kernel<<<blocks, threads>>>(
            (const float4*)feat, (const float4*)vals, w, (const int4*)rows,
            out, half, nQuads);
    }
    // Odd quad leftover (nQuads odd) — covers [2*half, nQuads).
    if (nQuads - 2 * half > 0) {
        int n = nQuads - 2 * half;
        scatter_dot_vec4_kernel<<<(n + 127) / 128, 128>>>(
            (const float4*)feat, (const float4*)vals, w, (const int4*)rows,
            out, 2 * half, nQuads);
    }
    const int tailStart = nQuads * 4;
    if (E - tailStart > 0) {
        int n = E - tailStart;
        scatter_dot_tail_kernel<<<(n + 255) / 256, 256>>>(
            feat, vals, w, rows, out, tailStart, E);
    }
}

// round 12
// speedup vs baseline: 1.4381x; 1.0759x over previous
#include <cuda_runtime.h>
#include <cuda_bf16.h>
#include <cstdint>

// Inputs (metadata order):
//   d_in[0] features  float32 [E*5]
//   d_in[1] values    float32 [E]
//   d_in[2] a0_weight float32 [5]
//   d_in[3] rows      int32   [E]
//   d_in[4] num_nodes int32   [1]
// Output: float32 [num_nodes]

// One-shot: each thread owns 4 consecutive edges (one "quad").
// 7 front-batched wide streaming loads (80B lane stride -> minimal L1tex
// wavefronts), then 4 REDGs. Proven fastest structure (R3/R6/R8 all 122.3us).
__global__ __launch_bounds__(128) void scatter_dot_vec4_kernel(
    const float4* __restrict__ feat4,  // [E*5/4]
    const float4* __restrict__ vals4,  // [E/4]
    const float*  __restrict__ w,      // [5]
    const int4*   __restrict__ rows4,  // [E/4]
    float* __restrict__ out,
    int nQuads)                        // E/4
{
    const float w0 = __ldg(w + 0);
    const float w1 = __ldg(w + 1);
    const float w2 = __ldg(w + 2);
    const float w3 = __ldg(w + 3);
    const float w4 = __ldg(w + 4);

    int q = blockIdx.x * blockDim.x + threadIdx.x;
    if (q >= nQuads) return;

    const float4 f0 = __ldcs(feat4 + (size_t)q * 5 + 0);
    const float4 f1 = __ldcs(feat4 + (size_t)q * 5 + 1);
    const float4 f2 = __ldcs(feat4 + (size_t)q * 5 + 2);
    const float4 f3 = __ldcs(feat4 + (size_t)q * 5 + 3);
    const float4 f4 = __ldcs(feat4 + (size_t)q * 5 + 4);
    const float4 v  = __ldcs(vals4 + q);
    const int4   r  = __ldcs(rows4 + q);

    // edge0: f0.x f0.y f0.z f0.w f1.x
    float d0 = w0*f0.x + w1*f0.y + w2*f0.z + w3*f0.w + w4*f1.x;
    // edge1: f1.y f1.z f1.w f2.x f2.y
    float d1 = w0*f1.y + w1*f1.z + w2*f1.w + w3*f2.x + w4*f2.y;
    // edge2: f2.z f2.w f3.x f3.y f3.z
    float d2 = w0*f2.z + w1*f2.w + w2*f3.x + w3*f3.y + w4*f3.z;
    // edge3: f3.w f4.x f4.y f4.z f4.w
    float d3 = w0*f3.w + w1*f4.x + w2*f4.y + w3*f4.z + w4*f4.w;

    atomicAdd(out + r.x, v.x * d0);
    atomicAdd(out + r.y, v.y * d1);
    atomicAdd(out + r.z, v.z * d2);
    atomicAdd(out + r.w, v.w * d3);
}

// Scalar tail for E % 4 != 0 (not hit for E = 2^24, kept for generality).
__global__ void scatter_dot_tail_kernel(
    const float* __restrict__ feat,
    const float* __restrict__ vals,
    const float* __restrict__ w,
    const int*   __restrict__ rows,
    float* __restrict__ out,
    int start, int E)
{
    int e = start + blockIdx.x * blockDim.x + threadIdx.x;
    if (e >= E) return;
    const float* f = feat + (size_t)e * 5;
    float d = vals[e] * (w[0]*f[0] + w[1]*f[1] + w[2]*f[2] + w[3]*f[3] + w[4]*f[4]);
    atomicAdd(out + rows[e], d);
}

extern "C" void kernel_launch(void* const* d_in, const int* in_sizes, int n_in,
                              void* d_out, int out_size)
{
    const float* feat = (const float*)d_in[0];
    const float* vals = (const float*)d_in[1];
    const float* w    = (const float*)d_in[2];
    const int*   rows = (const int*)d_in[3];
    float* out = (float*)d_out;

    const int E = in_sizes[1];          // values has E elements
    const int N = out_size;             // num_nodes

    // Zero the (poisoned) output via a memset node (cheaper than a kernel
    // launch; graph-capturable, no allocation).
    cudaMemsetAsync(out, 0, (size_t)N * sizeof(float), 0);

    const int nQuads = E / 4;
    if (nQuads > 0) {
        const int threads = 128;
        const int blocks = (nQuads + threads - 1) / threads;
        scatter_dot_vec4_kernel<<<blocks, threads>>>(
            (const float4*)feat, (const float4*)vals, w, (const int4*)rows,
            out, nQuads);
    }
    const int tailStart = nQuads * 4;
    if (E - tailStart > 0) {
        int n = E - tailStart;
        scatter_dot_tail_kernel<<<(n + 255) / 256, 256>>>(
            feat, vals, w, rows, out, tailStart, E);
    }
}

// round 14
// speedup vs baseline: 1.4455x; 1.0051x over previous
#include <cuda_runtime.h>
#include <cuda_bf16.h>
#include <cstdint>

// Inputs (metadata order):
//   d_in[0] features  float32 [E*5]
//   d_in[1] values    float32 [E]
//   d_in[2] a0_weight float32 [5]
//   d_in[3] rows      int32   [E]
//   d_in[4] num_nodes int32   [1]
// Output: float32 [num_nodes]

// Primary kernel: zero the poisoned output (grid-stride float4 + tail).
__global__ void zero_all_kernel(float* __restrict__ out, int n) {
    int n4 = n >> 2;
    float4* out4 = (float4*)out;
    int i = blockIdx.x * blockDim.x + threadIdx.x;
    int stride = gridDim.x * blockDim.x;
    for (int j = i; j < n4; j += stride)
        out4[j] = make_float4(0.f, 0.f, 0.f, 0.f);
    int t = n4 * 4 + i;
    if (t < n) out[t] = 0.f;
}

// Secondary kernel (PDL): front end (loads + math) runs CONCURRENTLY with the
// zeroing kernel; cudaGridDependencySynchronize() gates only the atomics.
// Structure otherwise identical to the proven 122us vec4 one-shot kernel.
__global__ __launch_bounds__(128) void scatter_dot_vec4_pdl_kernel(
    const float4* __restrict__ feat4,  // [E*5/4]
    const float4* __restrict__ vals4,  // [E/4]
    const float*  __restrict__ w,      // [5]
    const int4*   __restrict__ rows4,  // [E/4]
    float* __restrict__ out,
    int nQuads)                        // E/4
{
    const float w0 = __ldg(w + 0);
    const float w1 = __ldg(w + 1);
    const float w2 = __ldg(w + 2);
    const float w3 = __ldg(w + 3);
    const float w4 = __ldg(w + 4);

    int q = blockIdx.x * blockDim.x + threadIdx.x;
    if (q >= nQuads) {
        // All threads must still pass the dependency sync is NOT required —
        // cudaGridDependencySynchronize is per-thread; just exit.
        return;
    }

    const float4 f0 = __ldcs(feat4 + (size_t)q * 5 + 0);
    const float4 f1 = __ldcs(feat4 + (size_t)q * 5 + 1);
    const float4 f2 = __ldcs(feat4 + (size_t)q * 5 + 2);
    const float4 f3 = __ldcs(feat4 + (size_t)q * 5 + 3);
    const float4 f4 = __ldcs(feat4 + (size_t)q * 5 + 4);
    const float4 v  = __ldcs(vals4 + q);
    const int4   r  = __ldcs(rows4 + q);

    // edge0: f0.x f0.y f0.z f0.w f1.x
    float d0 = w0*f0.x + w1*f0.y + w2*f0.z + w3*f0.w + w4*f1.x;
    // edge1: f1.y f1.z f1.w f2.x f2.y
    float d1 = w0*f1.y + w1*f1.z + w2*f1.w + w3*f2.x + w4*f2.y;
    // edge2: f2.z f2.w f3.x f3.y f3.z
    float d2 = w0*f2.z + w1*f2.w + w2*f3.x + w3*f3.y + w4*f3.z;
    // edge3: f3.w f4.x f4.y f4.z f4.w
    float d3 = w0*f3.w + w1*f4.x + w2*f4.y + w3*f4.z + w4*f4.w;

    // Wait for the zeroing grid to fully complete before mutating out.
    cudaGridDependencySynchronize();

    atomicAdd(out + r.x, v.x * d0);
    atomicAdd(out + r.y, v.y * d1);
    atomicAdd(out + r.z, v.z * d2);
    atomicAdd(out + r.w, v.w * d3);
}

// Scalar tail for E % 4 != 0 (not hit for E = 2^24, kept for generality).
__global__ void scatter_dot_tail_kernel(
    const float* __restrict__ feat,
    const float* __restrict__ vals,
    const float* __restrict__ w,
    const int*   __restrict__ rows,
    float* __restrict__ out,
    int start, int E)
{
    int e = start + blockIdx.x * blockDim.x + threadIdx.x;
    if (e >= E) return;
    const float* f = feat + (size_t)e * 5;
    float d = vals[e] * (w[0]*f[0] + w[1]*f[1] + w[2]*f[2] + w[3]*f[3] + w[4]*f[4]);
    atomicAdd(out + rows[e], d);
}

extern "C" void kernel_launch(void* const* d_in, const int* in_sizes, int n_in,
                              void* d_out, int out_size)
{
    const float* feat = (const float*)d_in[0];
    const float* vals = (const float*)d_in[1];
    const float* w    = (const float*)d_in[2];
    const int*   rows = (const int*)d_in[3];
    float* out = (float*)d_out;

    const int E = in_sizes[1];          // values has E elements
    const int N = out_size;             // num_nodes

    // Primary: zero the (poisoned) output.
    {
        int zb = 256;
        int n4 = N >> 2;
        int zg = (n4 + zb - 1) / zb;
        if (zg > 4736) zg = 4736;
        if (zg < 1) zg = 1;
        zero_all_kernel<<<zg, zb>>>(out, N);
    }

    const int nQuads = E / 4;
    if (nQuads > 0) {
        const int threads = 128;
        const int blocks = (nQuads + threads - 1) / threads;

        // Secondary with programmatic dependent launch: overlap its load
        // front-end with the zeroing kernel; atomics gated in-kernel.
        cudaLaunchConfig_t cfg = {};
        cfg.gridDim  = dim3(blocks, 1, 1);
        cfg.blockDim = dim3(threads, 1, 1);
        cfg.dynamicSmemBytes = 0;
        cfg.stream = 0;
        cudaLaunchAttribute attrs[1];
        attrs[0].id = cudaLaunchAttributeProgrammaticStreamSerialization;
        attrs[0].val.programmaticStreamSerializationAllowed = 1;
        cfg.attrs = attrs;
        cfg.numAttrs = 1;

        cudaLaunchKernelEx(&cfg, scatter_dot_vec4_pdl_kernel,
                           (const float4*)feat, (const float4*)vals, w,
                           (const int4*)rows, out, nQuads);
    }
    const int tailStart = nQuads * 4;
    if (E - tailStart > 0) {
        int n = E - tailStart;
        scatter_dot_tail_kernel<<<(n + 255) / 256, 256>>>(
            feat, vals, w, rows, out, tailStart, E);
    }
}